// round 4
// baseline (speedup 1.0000x reference)
#include <cuda_runtime.h>

// LSTM_87067577025240 — Round 3: FFMA2 kernel, instruction-mix + coverage fixes.
//   * weights pre-duplicated per gate pair ({wg,wg,wi,wi} / {wf,wf,wo,wo}) so the
//     k-loop gets f32x2 operands straight from LDG.128 — no pack MOVs
//   * h pairs read via LDS.128 (4 -> effectively 3.5 LDS per k instead of 8)
//   * c state in registers (no cs smem traffic)
//   * NB=14 -> 147 CTAs on 148 SMs (was 128), scaling the FFMA2 issue floor
//     17.1 ms -> 14.9 ms

#define SEQ   256
#define H     512
#define B_TOT 2048
#define C_OUT 10
#define NB    14                          // batch columns per CTA
#define NBPAD 16                          // padded smem row stride (floats)
#define NCTA  ((B_TOT + NB - 1) / NB)     // 147 (last CTA handles 4 cols)
#define NPAIR (NB / 2)                    // 7 f32x2 pairs

typedef unsigned long long u64;

// Duplicated gate-pair weights:
//   g_Wgi[k*H + t] = {wgh[t][k], wgh[t][k], wih[t][k], wih[t][k]}
//   g_Wfo[k*H + t] = {wfh[t][k], wfh[t][k], woh[t][k], woh[t][k]}
__device__ __align__(16) float4 g_Wgi[H * H];
__device__ __align__(16) float4 g_Wfo[H * H];

__device__ __forceinline__ void unpack2(u64 v, float &lo, float &hi) {
    asm("mov.b64 {%0, %1}, %2;" : "=f"(lo), "=f"(hi) : "l"(v));
}
__device__ __forceinline__ u64 fma2(u64 a, u64 b, u64 c) {
    u64 d;
    asm("fma.rn.f32x2 %0, %1, %2, %3;" : "=l"(d) : "l"(a), "l"(b), "l"(c));
    return d;
}

// sigmoid / tanh built on MUFU.EX2 (rel err ~2^-22); avoids tanh.approx (2^-11)
// whose error would compound over 256 recurrent steps.
__device__ __forceinline__ float sigmoid_f(float x) {
    return 1.0f / (1.0f + __expf(-x));
}
__device__ __forceinline__ float tanh_f(float x) {
    float ax = fabsf(x);
    float e  = __expf(-2.0f * ax);
    float t  = (1.0f - e) / (1.0f + e);
    return copysignf(t, x);
}

__global__ void prepack_kernel(const float* __restrict__ wgh,
                               const float* __restrict__ wih,
                               const float* __restrict__ wfh,
                               const float* __restrict__ woh) {
    int id = blockIdx.x * blockDim.x + threadIdx.x;   // [0, H*H)
    int k  = id & (H - 1);
    int t  = id >> 9;
    float wg = wgh[t * H + k], wi = wih[t * H + k];
    float wf = wfh[t * H + k], wo = woh[t * H + k];
    g_Wgi[k * H + t] = make_float4(wg, wg, wi, wi);
    g_Wfo[k * H + t] = make_float4(wf, wf, wo, wo);
}

__global__ __launch_bounds__(H, 1)
void lstm_kernel(const float* __restrict__ x,
                 const float* __restrict__ wgx, const float* __restrict__ wix,
                 const float* __restrict__ wfx, const float* __restrict__ wox,
                 const float* __restrict__ bg,  const float* __restrict__ bi,
                 const float* __restrict__ bf,  const float* __restrict__ bo,
                 const float* __restrict__ wph, const float* __restrict__ bp,
                 const float* __restrict__ h_init, const float* __restrict__ c_init,
                 float* __restrict__ out) {
    __shared__ __align__(16) float hs[H * NBPAD];   // h[k][j], j < NB used
    __shared__ float xs[NBPAD];

    const int t    = threadIdx.x;        // h-row owned by this thread
    const int base = blockIdx.x * NB;    // first batch column of this CTA

    const float wgx_r = wgx[t], wix_r = wix[t], wfx_r = wfx[t], wox_r = wox[t];
    const float bg_r  = bg[t],  bi_r  = bi[t],  bf_r  = bf[t],  bo_r  = bo[t];

    const float h0 = h_init[t];
    const float c0 = c_init[t];
    float creg[NB];                      // c state lives in registers
#pragma unroll
    for (int j = 0; j < NB; j++) creg[j] = c0;
#pragma unroll
    for (int j = 0; j < NBPAD; j++) hs[t * NBPAD + j] = h0;
    if (t < NBPAD) xs[t] = 0.0f;
    __syncthreads();

    const ulonglong2* __restrict__ Wgi = reinterpret_cast<const ulonglong2*>(g_Wgi);
    const ulonglong2* __restrict__ Wfo = reinterpret_cast<const ulonglong2*>(g_Wfo);

    for (int s = 0; s < SEQ; s++) {
        if (t < NB) {
            const int b = base + t;
            xs[t] = (b < B_TOT) ? x[b * SEQ + s] : 0.0f;   // padded cols stay finite
        }

        u64 ag[NPAIR], ai[NPAIR], af[NPAIR], ao[NPAIR];
#pragma unroll
        for (int jp = 0; jp < NPAIR; jp++) { ag[jp] = 0ULL; ai[jp] = 0ULL; af[jp] = 0ULL; ao[jp] = 0ULL; }

        // gate pre-activations: acc[gate][j] += W[gate][t][k] * h[k][j]
#pragma unroll 4
        for (int k = 0; k < H; k++) {
            const ulonglong2 wgi = Wgi[k * H + t];   // {wg,wg},{wi,wi} — LDG.128
            const ulonglong2 wfo = Wfo[k * H + t];   // {wf,wf},{wo,wo} — LDG.128
            const float* hrow = &hs[k * NBPAD];
            const ulonglong2 h01 = reinterpret_cast<const ulonglong2*>(hrow)[0]; // LDS.128 bcast
            const ulonglong2 h23 = reinterpret_cast<const ulonglong2*>(hrow)[1];
            const ulonglong2 h45 = reinterpret_cast<const ulonglong2*>(hrow)[2];
            const u64        h6  = reinterpret_cast<const u64*>(hrow)[6];        // LDS.64
            const u64 hp[NPAIR] = { h01.x, h01.y, h23.x, h23.y, h45.x, h45.y, h6 };
#pragma unroll
            for (int jp = 0; jp < NPAIR; jp++) {
                ag[jp] = fma2(wgi.x, hp[jp], ag[jp]);
                ai[jp] = fma2(wgi.y, hp[jp], ai[jp]);
                af[jp] = fma2(wfo.x, hp[jp], af[jp]);
                ao[jp] = fma2(wfo.y, hp[jp], ao[jp]);
            }
        }
        __syncthreads();   // everyone done reading hs before we overwrite it

        // elementwise: gates -> (c, h) update for this thread's row
#pragma unroll
        for (int jp = 0; jp < NPAIR; jp++) {
            float pg0, pg1, pi0, pi1, pf0, pf1, po0, po1;
            unpack2(ag[jp], pg0, pg1);
            unpack2(ai[jp], pi0, pi1);
            unpack2(af[jp], pf0, pf1);
            unpack2(ao[jp], po0, po1);
#pragma unroll
            for (int hhalf = 0; hhalf < 2; hhalf++) {
                const int j  = jp * 2 + hhalf;
                const float pg = (hhalf ? pg1 : pg0);
                const float pi = (hhalf ? pi1 : pi0);
                const float pf = (hhalf ? pf1 : pf0);
                const float po = (hhalf ? po1 : po0);
                const float xv = xs[j];
                const float g = tanh_f   (pg + wgx_r * xv + bg_r);
                const float i = sigmoid_f(pi + wix_r * xv + bi_r);
                const float f = sigmoid_f(pf + wfx_r * xv + bf_r);
                const float o = sigmoid_f(po + wox_r * xv + bo_r);
                float c = creg[j];
                c = g * i + c * f;
                creg[j] = c;
                hs[t * NBPAD + j] = tanh_f(c) * o;
            }
        }
        __syncthreads();   // hs(t+1) complete before next step's k-loop / xs write
    }

    // final projection: out[b][c] = wph[c][:] . h[:, b] + bp[c]
    if (t < NB * C_OUT) {
        const int j = t / C_OUT;
        const int c = t - j * C_OUT;
        const int b = base + j;
        if (b < B_TOT) {
            float acc = bp[c];
#pragma unroll 8
            for (int k = 0; k < H; k++) acc += wph[c * H + k] * hs[k * NBPAD + j];
            out[b * C_OUT + c] = acc;
        }
    }
}

extern "C" void kernel_launch(void* const* d_in, const int* in_sizes, int n_in,
                              void* d_out, int out_size) {
    const float* x      = (const float*)d_in[0];
    const float* wgx    = (const float*)d_in[1];
    const float* wix    = (const float*)d_in[2];
    const float* wfx    = (const float*)d_in[3];
    const float* wox    = (const float*)d_in[4];
    const float* wgh    = (const float*)d_in[5];
    const float* wih    = (const float*)d_in[6];
    const float* wfh    = (const float*)d_in[7];
    const float* woh    = (const float*)d_in[8];
    const float* bg     = (const float*)d_in[9];
    const float* bi     = (const float*)d_in[10];
    const float* bf     = (const float*)d_in[11];
    const float* bo     = (const float*)d_in[12];
    const float* wph    = (const float*)d_in[13];
    const float* bp     = (const float*)d_in[14];
    const float* h_init = (const float*)d_in[15];
    const float* c_init = (const float*)d_in[16];
    float* out = (float*)d_out;

    prepack_kernel<<<(H * H) / 256, 256>>>(wgh, wih, wfh, woh);
    lstm_kernel<<<NCTA, H>>>(x, wgx, wix, wfx, wox, bg, bi, bf, bo,
                             wph, bp, h_init, c_init, out);
}

// round 5
// speedup vs baseline: 1.1262x; 1.1262x over previous
#include <cuda_runtime.h>

// LSTM_87067577025240 — Round 4: FFMA2 persistent kernel, latency-hiding fix.
//   * REVERT weight duplication (R3 doubled L2 traffic to the LTS cap — regression)
//   * depth-4 register prefetch ring on the weight stream: 4 LDG.128 always in
//     flight, hiding the ~250-cyc L2 latency that cost R1 ~26% over its floor
//   * NB=14 -> 147 CTAs on 148 SMs (FFMA2 issue floor 17.1 -> 14.9 ms)
//   * c state in smem (keeps regs < 128; R3's reg pressure caused spills)
//   * hs(32KB)+cs(28KB) -> 60KB dynamic smem via cudaFuncSetAttribute

#define SEQ   256
#define H     512
#define B_TOT 2048
#define C_OUT 10
#define NB    14                          // batch columns per CTA
#define NBPAD 16                          // hs row stride (floats), 64B-aligned rows
#define NCTA  ((B_TOT + NB - 1) / NB)     // 147
#define NPAIR (NB / 2)                    // 7 f32x2 pairs
#define PF    4                           // weight prefetch depth

typedef unsigned long long u64;

// Gate-fused transposed weights, padded by PF rows so the prefetch ring can
// over-read harmlessly: g_Wt[k*H + t] = {wgh[t][k], wih[t][k], wfh[t][k], woh[t][k]}
__device__ __align__(16) float4 g_Wt[(H + PF) * H];

__device__ __forceinline__ u64 pack2(float lo, float hi) {
    u64 r;
    asm("mov.b64 %0, {%1, %2};" : "=l"(r) : "f"(lo), "f"(hi));
    return r;
}
__device__ __forceinline__ void unpack2(u64 v, float &lo, float &hi) {
    asm("mov.b64 {%0, %1}, %2;" : "=f"(lo), "=f"(hi) : "l"(v));
}
__device__ __forceinline__ u64 fma2(u64 a, u64 b, u64 c) {
    u64 d;
    asm("fma.rn.f32x2 %0, %1, %2, %3;" : "=l"(d) : "l"(a), "l"(b), "l"(c));
    return d;
}

// sigmoid / tanh built on MUFU.EX2 (rel err ~2^-22); avoids tanh.approx (2^-11)
// whose error would compound over 256 recurrent steps.
__device__ __forceinline__ float sigmoid_f(float x) {
    return 1.0f / (1.0f + __expf(-x));
}
__device__ __forceinline__ float tanh_f(float x) {
    float ax = fabsf(x);
    float e  = __expf(-2.0f * ax);
    float t  = (1.0f - e) / (1.0f + e);
    return copysignf(t, x);
}

__global__ void prepack_kernel(const float* __restrict__ wgh,
                               const float* __restrict__ wih,
                               const float* __restrict__ wfh,
                               const float* __restrict__ woh) {
    int id = blockIdx.x * blockDim.x + threadIdx.x;   // [0, H*H)
    int k  = id & (H - 1);
    int t  = id >> 9;
    g_Wt[k * H + t] = make_float4(wgh[t * H + k], wih[t * H + k],
                                  wfh[t * H + k], woh[t * H + k]);
}

__global__ __launch_bounds__(H, 1)
void lstm_kernel(const float* __restrict__ x,
                 const float* __restrict__ wgx, const float* __restrict__ wix,
                 const float* __restrict__ wfx, const float* __restrict__ wox,
                 const float* __restrict__ bg,  const float* __restrict__ bi,
                 const float* __restrict__ bf,  const float* __restrict__ bo,
                 const float* __restrict__ wph, const float* __restrict__ bp,
                 const float* __restrict__ h_init, const float* __restrict__ c_init,
                 float* __restrict__ out) {
    extern __shared__ __align__(16) float smem[];
    float* hs = smem;              // [H][NBPAD] h state, broadcast-read in k-loop
    float* cs = smem + H * NBPAD;  // [H][NB]    c state
    float* xs = cs + H * NB;       // [NBPAD]    current x per column

    const int t    = threadIdx.x;        // h-row owned by this thread
    const int base = blockIdx.x * NB;    // first batch column of this CTA

    const float wgx_r = wgx[t], wix_r = wix[t], wfx_r = wfx[t], wox_r = wox[t];
    const float bg_r  = bg[t],  bi_r  = bi[t],  bf_r  = bf[t],  bo_r  = bo[t];

    const float h0 = h_init[t];
    const float c0 = c_init[t];
#pragma unroll
    for (int j = 0; j < NBPAD; j++) hs[t * NBPAD + j] = h0;
#pragma unroll
    for (int j = 0; j < NB; j++)    cs[t * NB + j] = c0;
    if (t < NBPAD) xs[t] = 0.0f;
    __syncthreads();

    const float4* __restrict__ Wt = g_Wt;

    for (int s = 0; s < SEQ; s++) {
        if (t < NB) {
            const int b = base + t;
            xs[t] = (b < B_TOT) ? x[b * SEQ + s] : 0.0f;
        }

        u64 ag[NPAIR], ai[NPAIR], af[NPAIR], ao[NPAIR];
#pragma unroll
        for (int jp = 0; jp < NPAIR; jp++) { ag[jp] = 0ULL; ai[jp] = 0ULL; af[jp] = 0ULL; ao[jp] = 0ULL; }

        // prime the prefetch ring: PF weight rows in flight at all times
        float4 wbuf[PF];
#pragma unroll
        for (int i = 0; i < PF; i++) wbuf[i] = Wt[i * H + t];

#pragma unroll 1
        for (int kg = 0; kg < H; kg += PF) {
#pragma unroll
            for (int i = 0; i < PF; i++) {
                const int k = kg + i;
                const float4 w = wbuf[i];
                wbuf[i] = Wt[(k + PF) * H + t];   // over-reads land in the pad rows
                const u64 wg2 = pack2(w.x, w.x);
                const u64 wi2 = pack2(w.y, w.y);
                const u64 wf2 = pack2(w.z, w.z);
                const u64 wo2 = pack2(w.w, w.w);
                const float* hrow = &hs[k * NBPAD];
                const ulonglong2 h01 = *reinterpret_cast<const ulonglong2*>(hrow);     // LDS.128 bcast
                const ulonglong2 h23 = *reinterpret_cast<const ulonglong2*>(hrow + 4);
                const ulonglong2 h45 = *reinterpret_cast<const ulonglong2*>(hrow + 8);
                const u64        h6  = *reinterpret_cast<const u64*>(hrow + 12);       // LDS.64
                ag[0] = fma2(wg2, h01.x, ag[0]); ai[0] = fma2(wi2, h01.x, ai[0]);
                af[0] = fma2(wf2, h01.x, af[0]); ao[0] = fma2(wo2, h01.x, ao[0]);
                ag[1] = fma2(wg2, h01.y, ag[1]); ai[1] = fma2(wi2, h01.y, ai[1]);
                af[1] = fma2(wf2, h01.y, af[1]); ao[1] = fma2(wo2, h01.y, ao[1]);
                ag[2] = fma2(wg2, h23.x, ag[2]); ai[2] = fma2(wi2, h23.x, ai[2]);
                af[2] = fma2(wf2, h23.x, af[2]); ao[2] = fma2(wo2, h23.x, ao[2]);
                ag[3] = fma2(wg2, h23.y, ag[3]); ai[3] = fma2(wi2, h23.y, ai[3]);
                af[3] = fma2(wf2, h23.y, af[3]); ao[3] = fma2(wo2, h23.y, ao[3]);
                ag[4] = fma2(wg2, h45.x, ag[4]); ai[4] = fma2(wi2, h45.x, ai[4]);
                af[4] = fma2(wf2, h45.x, af[4]); ao[4] = fma2(wo2, h45.x, ao[4]);
                ag[5] = fma2(wg2, h45.y, ag[5]); ai[5] = fma2(wi2, h45.y, ai[5]);
                af[5] = fma2(wf2, h45.y, af[5]); ao[5] = fma2(wo2, h45.y, ao[5]);
                ag[6] = fma2(wg2, h6,    ag[6]); ai[6] = fma2(wi2, h6,    ai[6]);
                af[6] = fma2(wf2, h6,    af[6]); ao[6] = fma2(wo2, h6,    ao[6]);
            }
        }
        __syncthreads();   // everyone done reading hs before we overwrite it

        // elementwise: gates -> (c, h) update for this thread's row
#pragma unroll
        for (int jp = 0; jp < NPAIR; jp++) {
            float pg0, pg1, pi0, pi1, pf0, pf1, po0, po1;
            unpack2(ag[jp], pg0, pg1);
            unpack2(ai[jp], pi0, pi1);
            unpack2(af[jp], pf0, pf1);
            unpack2(ao[jp], po0, po1);
#pragma unroll
            for (int hhalf = 0; hhalf < 2; hhalf++) {
                const int j  = jp * 2 + hhalf;
                const float pg = (hhalf ? pg1 : pg0);
                const float pi = (hhalf ? pi1 : pi0);
                const float pf = (hhalf ? pf1 : pf0);
                const float po = (hhalf ? po1 : po0);
                const float xv = xs[j];
                const float g = tanh_f   (pg + wgx_r * xv + bg_r);
                const float i = sigmoid_f(pi + wix_r * xv + bi_r);
                const float f = sigmoid_f(pf + wfx_r * xv + bf_r);
                const float o = sigmoid_f(po + wox_r * xv + bo_r);
                float c = cs[t * NB + j];
                c = g * i + c * f;
                cs[t * NB + j] = c;
                hs[t * NBPAD + j] = tanh_f(c) * o;
            }
        }
        __syncthreads();   // hs(t+1) complete before next step's k-loop / xs write
    }

    // final projection: out[b][c] = wph[c][:] . h[:, b] + bp[c]
    if (t < NB * C_OUT) {
        const int j = t / C_OUT;
        const int c = t - j * C_OUT;
        const int b = base + j;
        if (b < B_TOT) {
            float acc = bp[c];
#pragma unroll 8
            for (int k = 0; k < H; k++) acc += wph[c * H + k] * hs[k * NBPAD + j];
            out[b * C_OUT + c] = acc;
        }
    }
}

extern "C" void kernel_launch(void* const* d_in, const int* in_sizes, int n_in,
                              void* d_out, int out_size) {
    const float* x      = (const float*)d_in[0];
    const float* wgx    = (const float*)d_in[1];
    const float* wix    = (const float*)d_in[2];
    const float* wfx    = (const float*)d_in[3];
    const float* wox    = (const float*)d_in[4];
    const float* wgh    = (const float*)d_in[5];
    const float* wih    = (const float*)d_in[6];
    const float* wfh    = (const float*)d_in[7];
    const float* woh    = (const float*)d_in[8];
    const float* bg     = (const float*)d_in[9];
    const float* bi     = (const float*)d_in[10];
    const float* bf     = (const float*)d_in[11];
    const float* bo     = (const float*)d_in[12];
    const float* wph    = (const float*)d_in[13];
    const float* bp     = (const float*)d_in[14];
    const float* h_init = (const float*)d_in[15];
    const float* c_init = (const float*)d_in[16];
    float* out = (float*)d_out;

    const int smem_bytes = (H * NBPAD + H * NB + NBPAD) * (int)sizeof(float); // ~61.5KB
    cudaFuncSetAttribute(lstm_kernel, cudaFuncAttributeMaxDynamicSharedMemorySize, smem_bytes);

    prepack_kernel<<<(H * H) / 256, 256>>>(wgh, wih, wfh, woh);
    lstm_kernel<<<NCTA, H, smem_bytes>>>(x, wgx, wix, wfx, wox, bg, bi, bf, bo,
                                         wph, bp, h_init, c_init, out);
}